// round 3
// baseline (speedup 1.0000x reference)
#include <cuda_runtime.h>
#include <math.h>

#define B_  8
#define C_  64
#define H_  48
#define W_  48
#define S_  2304
#define NH_ 4
#define EPS_ 1.1920929e-07f

// ---------------- scratch (device globals; no allocation allowed) ----------
__device__ __align__(16) float g_wT[C_*9*C_];     // conv weights [ci*9+k][co]
__device__ __align__(16) float g_qc[B_*S_*C_];    // conv output   [b][p][c]
__device__ __align__(16) float g_qp[B_*C_*S_];    // proj q        [b][e][p]
__device__ __align__(16) float g_kp[B_*C_*S_];    // proj k        [b][e][p]
__device__ __align__(16) float g_vt[B_*S_*C_];    // v transposed  [b][p][c]
__device__ float g_l[B_*S_*NH_];                  // softmax denom [b][i][h]

// ---------------- weight transpose: [co][ci][3][3] -> [ci*9+k][co] ---------
__global__ void wt_kernel(const float* __restrict__ w) {
    int idx = blockIdx.x * 256 + threadIdx.x;   // 36864 total
    if (idx >= C_*9*C_) return;
    int co = idx & 63;
    int rk = idx >> 6;        // ci*9 + k
    g_wT[idx] = w[co*(C_*9) + rk];
}

// ---------------- conv 3x3 SAME, writes transposed [b][p][c] ---------------
__global__ void __launch_bounds__(256) conv_kernel(const float* __restrict__ q) {
    int b = blockIdx.x / H_;
    int h = blockIdx.x % H_;
    __shared__ float in_s[3][C_][W_];     // 36 KB
    const float* qb = q + (size_t)b*C_*H_*W_;
    for (int fl = threadIdx.x; fl < 3*C_*W_; fl += 256) {
        int r = fl / (C_*W_);
        int c = (fl / W_) % C_;
        int w = fl % W_;
        int hy = h + r - 1;
        in_s[r][c][w] = (hy >= 0 && hy < H_) ? qb[c*H_*W_ + hy*W_ + w] : 0.f;
    }
    __syncthreads();

    int co   = threadIdx.x & 63;
    int wg   = threadIdx.x >> 6;    // 0..3
    int base = wg * 12;

    float acc[12];
#pragma unroll
    for (int u = 0; u < 12; u++) acc[u] = 0.f;

    for (int ci = 0; ci < C_; ci++) {
#pragma unroll
        for (int r = 0; r < 3; r++) {
            float xi[14];
#pragma unroll
            for (int u = 0; u < 14; u++) {
                int x = base - 1 + u;
                xi[u] = (x >= 0 && x < W_) ? in_s[r][ci][x] : 0.f;
            }
            const float* wrow = &g_wT[(ci*9 + r*3)*C_ + co];
#pragma unroll
            for (int kw = 0; kw < 3; kw++) {
                float wv = wrow[kw*C_];
#pragma unroll
                for (int ww = 0; ww < 12; ww++) acc[ww] += xi[ww + kw] * wv;
            }
        }
    }
    float* outp = g_qc + ((size_t)b*S_ + h*W_ + base)*C_ + co;
#pragma unroll
    for (int ww = 0; ww < 12; ww++) outp[ww*C_] = acc[ww];
}

// ---------------- rmsnorm + linear projection -------------------------------
// IS_Q: read g_qc ([b][p][c] layout), write g_qp, scale=0.25
// !IS_Q: read xin  ([b][c][p] layout), write g_kp, scale=1
template <bool IS_Q>
__global__ void __launch_bounds__(256) normproj_kernel(
        const float* __restrict__ xin,
        const float* __restrict__ wmat,
        const float* __restrict__ nw,
        const float* __restrict__ bias,
        float scale)
{
    int b  = blockIdx.y;
    int p0 = blockIdx.x * 32;
    __shared__ float wm[64*65];
    __shared__ __align__(16) float xs[32*68];
    __shared__ float rinv[32];
    __shared__ float bs[64];
    int tid = threadIdx.x;

    for (int fl = tid; fl < 4096; fl += 256) {
        int e = fl >> 6, c = fl & 63;
        wm[e*65 + c] = wmat[fl] * nw[c];      // fold norm weight into matrix
    }
    if (tid < 64) bs[tid] = bias[tid];

    if (IS_Q) {
        const float4* src = (const float4*)(g_qc + ((size_t)b*S_ + p0)*C_);
        for (int fl = tid; fl < 512; fl += 256) {
            int i = fl >> 4, c4 = fl & 15;
            float4 v = src[i*16 + c4];
            float* d = &xs[i*68 + c4*4];
            d[0] = v.x; d[1] = v.y; d[2] = v.z; d[3] = v.w;
        }
    } else {
        const float* src = xin + (size_t)b*C_*S_ + p0;
        for (int fl = tid; fl < 2048; fl += 256) {
            int c = fl >> 5, i = fl & 31;
            xs[i*68 + c] = src[c*S_ + i];
        }
    }
    __syncthreads();

    {   // sum of squares per position (8 lanes per position)
        int i = tid >> 3, sub = tid & 7;
        float ss = 0.f;
#pragma unroll
        for (int u = 0; u < 8; u++) { float v = xs[i*68 + sub*8 + u]; ss += v*v; }
#pragma unroll
        for (int m = 4; m >= 1; m >>= 1) ss += __shfl_xor_sync(0xffffffffu, ss, m);
        if (sub == 0) rinv[i] = rsqrtf(ss * (1.f/64.f) + EPS_);
    }
    __syncthreads();

    int e  = tid & 63;
    int ig = tid >> 6;   // 0..3
    float* dst = (IS_Q ? g_qp : g_kp) + (size_t)b*C_*S_ + e*S_ + p0;
#pragma unroll
    for (int rep = 0; rep < 8; rep++) {
        int i = rep*4 + ig;
        float acc = 0.f;
#pragma unroll
        for (int c = 0; c < 64; c++) acc += xs[i*68 + c] * wm[e*65 + c];
        dst[i] = (acc * rinv[i] + bs[e]) * scale;
    }
}

// ---------------- v transpose: [b][c][p] -> [b][p][c] -----------------------
__global__ void __launch_bounds__(256) vtrans_kernel(const float* __restrict__ v) {
    int b  = blockIdx.y;
    int p0 = blockIdx.x * 32;
    __shared__ __align__(16) float xs[32*68];
    int tid = threadIdx.x;
    const float* src = v + (size_t)b*C_*S_ + p0;
    for (int fl = tid; fl < 2048; fl += 256) {
        int c = fl >> 5, i = fl & 31;
        xs[i*68 + c] = src[c*S_ + i];
    }
    __syncthreads();
    float4* dst = (float4*)(g_vt + ((size_t)b*S_ + p0)*C_);
    for (int fl = tid; fl < 512; fl += 256) {
        int i = fl >> 4, c4 = fl & 15;
        float* s = &xs[i*68 + c4*4];
        dst[i*16 + c4] = make_float4(s[0], s[1], s[2], s[3]);
    }
}

// ---------------- pass 1: per-head softmax denominators ---------------------
__global__ void __launch_bounds__(256) attn_l_kernel() {
    int b  = blockIdx.y;
    int i0 = blockIdx.x * 64;
    __shared__ __align__(16) float qsT[64*68];   // [c][i]
    __shared__ __align__(16) float ksT[64*68];   // [c][j]
    int tid = threadIdx.x;
    int tx = tid & 15, ty = tid >> 4;

    for (int fl = tid; fl < 4096; fl += 256) {
        int c = fl >> 6, i = fl & 63;
        qsT[c*68 + i] = g_qp[(size_t)b*C_*S_ + c*S_ + i0 + i];
    }

    float lacc[4][4];
#pragma unroll
    for (int a = 0; a < 4; a++)
#pragma unroll
        for (int h = 0; h < 4; h++) lacc[a][h] = 0.f;

    for (int kt = 0; kt < S_/64; kt++) {
        __syncthreads();
        for (int fl = tid; fl < 4096; fl += 256) {
            int c = fl >> 6, j = fl & 63;
            ksT[c*68 + j] = g_kp[(size_t)b*C_*S_ + c*S_ + kt*64 + j];
        }
        __syncthreads();
#pragma unroll
        for (int h = 0; h < 4; h++) {
            float s[4][4];
#pragma unroll
            for (int a = 0; a < 4; a++)
#pragma unroll
                for (int bb = 0; bb < 4; bb++) s[a][bb] = 0.f;
#pragma unroll
            for (int cc = 0; cc < 16; cc++) {
                int c = h*16 + cc;
                float4 qv = *(const float4*)&qsT[c*68 + 4*ty];
                float4 kv = *(const float4*)&ksT[c*68 + 4*tx];
                float qa[4] = {qv.x, qv.y, qv.z, qv.w};
                float ka[4] = {kv.x, kv.y, kv.z, kv.w};
#pragma unroll
                for (int a = 0; a < 4; a++)
#pragma unroll
                    for (int bb = 0; bb < 4; bb++) s[a][bb] += qa[a]*ka[bb];
            }
#pragma unroll
            for (int a = 0; a < 4; a++)
#pragma unroll
                for (int bb = 0; bb < 4; bb++) lacc[a][h] += __expf(s[a][bb]);
        }
    }
#pragma unroll
    for (int a = 0; a < 4; a++)
#pragma unroll
        for (int h = 0; h < 4; h++) {
            float v = lacc[a][h];
#pragma unroll
            for (int m = 8; m >= 1; m >>= 1) v += __shfl_xor_sync(0xffffffffu, v, m);
            if (tx == 0) g_l[((size_t)b*S_ + i0 + 4*ty + a)*NH_ + h] = v;
        }
}

// ---------------- pass 2: weights + W@V -------------------------------------
__global__ void __launch_bounds__(256) attn_out_kernel(float* __restrict__ outp) {
    int b  = blockIdx.y;
    int i0 = blockIdx.x * 64;
    __shared__ __align__(16) float qsT[64*68];   // [c][i]   17408 B
    __shared__ __align__(16) float ksT[64*36];   // [c][j32]  9216 B
    __shared__ __align__(16) float vs [32*64];   // [j][d]    8192 B
    __shared__ __align__(16) float ws [64*33];   // [i][j32]  8448 B
    int tid = threadIdx.x;
    int tx = tid & 15, ty = tid >> 4;

    for (int fl = tid; fl < 4096; fl += 256) {
        int c = fl >> 6, i = fl & 63;
        qsT[c*68 + i] = g_qp[(size_t)b*C_*S_ + c*S_ + i0 + i];
    }

    float linv[4][4];
#pragma unroll
    for (int a = 0; a < 4; a++)
#pragma unroll
        for (int h = 0; h < 4; h++)
            linv[a][h] = 0.25f / g_l[((size_t)b*S_ + i0 + 4*ty + a)*NH_ + h];

    float4 acc[4];
#pragma unroll
    for (int a = 0; a < 4; a++) acc[a] = make_float4(0.f, 0.f, 0.f, 0.f);

    for (int kt = 0; kt < S_/32; kt++) {
        __syncthreads();
        for (int fl = tid; fl < 2048; fl += 256) {
            int c = fl >> 5, j = fl & 31;
            ksT[c*36 + j] = g_kp[(size_t)b*C_*S_ + c*S_ + kt*32 + j];
        }
        {
            const float4* src = (const float4*)(g_vt + ((size_t)b*S_ + kt*32)*C_);
            float4* d = (float4*)vs;
            for (int fl = tid; fl < 512; fl += 256) d[fl] = src[fl];
        }
        __syncthreads();

        float w[4][2];
#pragma unroll
        for (int a = 0; a < 4; a++) { w[a][0] = 0.f; w[a][1] = 0.f; }
#pragma unroll
        for (int h = 0; h < 4; h++) {
            float s[4][2];
#pragma unroll
            for (int a = 0; a < 4; a++) { s[a][0] = 0.f; s[a][1] = 0.f; }
#pragma unroll
            for (int cc = 0; cc < 16; cc++) {
                int c = h*16 + cc;
                float4 qv = *(const float4*)&qsT[c*68 + 4*ty];
                float2 kv = *(const float2*)&ksT[c*36 + 2*tx];
                float qa[4] = {qv.x, qv.y, qv.z, qv.w};
#pragma unroll
                for (int a = 0; a < 4; a++) {
                    s[a][0] += qa[a]*kv.x;
                    s[a][1] += qa[a]*kv.y;
                }
            }
#pragma unroll
            for (int a = 0; a < 4; a++) {
                w[a][0] += __expf(s[a][0]) * linv[a][h];
                w[a][1] += __expf(s[a][1]) * linv[a][h];
            }
        }
#pragma unroll
        for (int a = 0; a < 4; a++) {
            ws[(4*ty + a)*33 + 2*tx + 0] = w[a][0];
            ws[(4*ty + a)*33 + 2*tx + 1] = w[a][1];
        }
        __syncthreads();

#pragma unroll
        for (int j = 0; j < 32; j++) {
            float4 vv = *(const float4*)&vs[j*64 + 4*tx];
#pragma unroll
            for (int a = 0; a < 4; a++) {
                float wv = ws[(4*ty + a)*33 + j];
                acc[a].x += wv*vv.x; acc[a].y += wv*vv.y;
                acc[a].z += wv*vv.z; acc[a].w += wv*vv.w;
            }
        }
    }
#pragma unroll
    for (int a = 0; a < 4; a++) {
        float4* d = (float4*)(outp + ((size_t)b*S_ + i0 + 4*ty + a)*C_ + 4*tx);
        *d = acc[a];
    }
}

// ---------------- launch -----------------------------------------------------
extern "C" void kernel_launch(void* const* d_in, const int* in_sizes, int n_in,
                              void* d_out, int out_size) {
    const float* q      = (const float*)d_in[0];
    const float* k      = (const float*)d_in[1];
    const float* v      = (const float*)d_in[2];
    const float* conv_w = (const float*)d_in[3];
    const float* nq_w   = (const float*)d_in[4];
    const float* nk_w   = (const float*)d_in[5];
    const float* wq     = (const float*)d_in[6];
    const float* bq     = (const float*)d_in[7];
    const float* wk     = (const float*)d_in[8];
    const float* bk     = (const float*)d_in[9];
    float* outp = (float*)d_out;
    (void)in_sizes; (void)n_in; (void)out_size;

    wt_kernel<<<(C_*9*C_ + 255)/256, 256>>>(conv_w);
    conv_kernel<<<B_*H_, 256>>>(q);
    vtrans_kernel<<<dim3(S_/32, B_), 256>>>(v);
    normproj_kernel<true ><<<dim3(S_/32, B_), 256>>>(nullptr, wq, nq_w, bq, 0.25f);
    normproj_kernel<false><<<dim3(S_/32, B_), 256>>>(k,       wk, nk_w, bk, 1.0f);
    attn_l_kernel  <<<dim3(S_/64, B_), 256>>>();
    attn_out_kernel<<<dim3(S_/64, B_), 256>>>(outp);
}